// round 12
// baseline (speedup 1.0000x reference)
#include <cuda_runtime.h>
#include <cstdint>
#include <math.h>

// Problem constants
#define T_  1024
#define H_  1024
#define E_  16
#define K_  4
#define I_  1408
#define IS_ 2816

// ---------------------------------------------------------------------------
// Device scratch (static globals — no runtime allocation allowed)
// ---------------------------------------------------------------------------
__device__ int   g_cnt[E_];                       // tokens per expert
__device__ int   g_tok[E_ * T_];                  // per-expert token lists
__device__ float g_wt [E_ * T_];                  // per-assignment combine weight
__device__ float g_act[(size_t)E_ * T_ * I_];     // routed SwiGLU acts (weight-folded)
__device__ float g_shact[(size_t)T_ * IS_];       // shared-expert activations

// ---------------------------------------------------------------------------
// Helpers
// ---------------------------------------------------------------------------
__device__ __forceinline__ float siluf(float g) { return g / (1.f + __expf(-g)); }

// tf32 round (rna) of a float4, raw bits
__device__ __forceinline__ uint4 tf32x4(float4 v) {
    uint4 u;
    asm("cvt.rna.tf32.f32 %0, %1;" : "=r"(u.x) : "f"(v.x));
    asm("cvt.rna.tf32.f32 %0, %1;" : "=r"(u.y) : "f"(v.y));
    asm("cvt.rna.tf32.f32 %0, %1;" : "=r"(u.z) : "f"(v.z));
    asm("cvt.rna.tf32.f32 %0, %1;" : "=r"(u.w) : "f"(v.w));
    return u;
}

// m16n8k8 tf32 MMA, D += A*B (fp32 accum in regs)
__device__ __forceinline__ void mma8(float* d, const uint32_t* a, const uint32_t* b) {
    asm volatile(
        "mma.sync.aligned.m16n8k8.row.col.f32.tf32.tf32.f32 "
        "{%0,%1,%2,%3}, {%4,%5,%6,%7}, {%8,%9}, {%0,%1,%2,%3};"
        : "+f"(d[0]), "+f"(d[1]), "+f"(d[2]), "+f"(d[3])
        : "r"(a[0]), "r"(a[1]), "r"(a[2]), "r"(a[3]), "r"(b[0]), "r"(b[1]));
}

#define FB(x) __float_as_uint(x)

// ---------------------------------------------------------------------------
// Kernel 0: reset per-expert counters
// ---------------------------------------------------------------------------
__global__ void zero_cnt_kernel() {
    if (threadIdx.x < E_) g_cnt[threadIdx.x] = 0;
}

// ---------------------------------------------------------------------------
// Kernel 1: gating (exact fp32 — routing must match the reference bit-wise)
// ---------------------------------------------------------------------------
__global__ void __launch_bounds__(128) gate_kernel(
    const float* __restrict__ X,
    const float* __restrict__ GW,
    const float* __restrict__ GB)
{
    __shared__ float xs[H_];
    __shared__ float sl[E_];
    const int t = blockIdx.x;
    const int tid = threadIdx.x;

    #pragma unroll
    for (int q = 0; q < 2; q++) {
        int i = (tid + q * 128) * 4;
        *(float4*)&xs[i] = *(const float4*)(X + (size_t)t * H_ + i);
    }
    __syncthreads();

    const int warp = tid >> 5, lane = tid & 31;
    #pragma unroll
    for (int sub = 0; sub < 4; sub++) {
        int e = warp * 4 + sub;
        const float* w = GW + (size_t)e * H_;
        float s = 0.f;
        for (int k = lane * 4; k < H_; k += 128) {
            float4 xv = *(const float4*)&xs[k];
            float4 wv = *(const float4*)(w + k);
            s = fmaf(xv.x, wv.x, s); s = fmaf(xv.y, wv.y, s);
            s = fmaf(xv.z, wv.z, s); s = fmaf(xv.w, wv.w, s);
        }
        #pragma unroll
        for (int o = 16; o > 0; o >>= 1) s += __shfl_xor_sync(0xffffffffu, s, o);
        if (lane == 0) sl[e] = s;
    }
    __syncthreads();

    if (tid == 0) {
        float sc[E_], sfc[E_];
        #pragma unroll
        for (int e = 0; e < E_; e++) {
            sc[e]  = 1.f / (1.f + __expf(-sl[e]));
            sfc[e] = sc[e] + GB[e];
        }
        float gs[4];
        #pragma unroll
        for (int g = 0; g < 4; g++) {
            float m1 = -1e30f, m2 = -1e30f;
            #pragma unroll
            for (int j = 0; j < 4; j++) {
                float v = sfc[g * 4 + j];
                if (v > m1) { m2 = m1; m1 = v; } else if (v > m2) m2 = v;
            }
            gs[g] = m1 + m2;
        }
        int g1 = 0;
        for (int g = 1; g < 4; g++) if (gs[g] > gs[g1]) g1 = g;
        int g2 = -1;
        for (int g = 0; g < 4; g++) {
            if (g == g1) continue;
            if (g2 < 0 || gs[g] > gs[g2]) g2 = g;
        }
        float tmp[E_];
        #pragma unroll
        for (int e = 0; e < E_; e++) {
            int gg = e >> 2;
            tmp[e] = (gg == g1 || gg == g2) ? sfc[e] : 0.f;
        }
        int   idx[K_];
        float wv[K_];
        float wsum = 0.f;
        #pragma unroll
        for (int k = 0; k < K_; k++) {
            int best = 0; float bv = -1e30f;
            #pragma unroll
            for (int e = 0; e < E_; e++) if (tmp[e] > bv) { bv = tmp[e]; best = e; }
            idx[k] = best; wv[k] = sc[best]; wsum += sc[best];
            tmp[best] = -1e30f;
        }
        float inv = 1.f / (wsum + 1e-20f);
        #pragma unroll
        for (int k = 0; k < K_; k++) {
            int e = idx[k];
            int slot = atomicAdd(&g_cnt[e], 1);
            g_tok[e * T_ + slot] = t;
            g_wt [e * T_ + slot] = wv[k] * inv;
        }
    }
}

// ---------------------------------------------------------------------------
// Kernel 2: mlp1 — tf32 mma.sync grouped GEMM, dual-B (gate+up), fused SwiGLU.
// Block tile 128(M) x 64(N per matrix), BK=16, 256 thr (8 warps, 2x4).
// Warp tile 64x16 per matrix (4 m16 x 2 n8 mma tiles). Double-buffered smem.
// Combine weight folded into routed activations.
// ---------------------------------------------------------------------------
template<bool ROUTED, int NTOT>
__global__ void __launch_bounds__(256, 2) mlp1_tc(
    const float* __restrict__ X,
    const float* __restrict__ Wg,
    const float* __restrict__ Wu)
{
    constexpr int BK = 16, NC = H_ / BK, SK = 20;  // padded stride (conflict-free)

    const int e  = ROUTED ? blockIdx.z : 0;
    const int ne = ROUTED ? g_cnt[e] : T_;
    const int m0 = blockIdx.y * 128;
    if (m0 >= ne) return;
    const int n0 = blockIdx.x * 64;

    __shared__ __align__(16) float As[2][128][SK];
    __shared__ __align__(16) float Bg[2][64][SK];
    __shared__ __align__(16) float Bu[2][64][SK];
    __shared__ int   stok[128];
    __shared__ float swt[128];

    const float* wg = Wg + (size_t)e * NTOT * H_;
    const float* wu = Wu + (size_t)e * NTOT * H_;
    float* aout = ROUTED ? (g_act + (size_t)e * T_ * NTOT) : g_shact;

    const int tid = threadIdx.x, wid = tid >> 5, lid = tid & 31;
    const int wm = wid & 1, wn = wid >> 1;
    const int gp = lid >> 2, tg = lid & 3;

    if (tid < 128) {
        int r = m0 + tid;
        if (ROUTED) {
            stok[tid] = (r < ne) ? g_tok[e * T_ + r] : 0;
            swt[tid]  = (r < ne) ? g_wt [e * T_ + r] : 0.f;
        } else {
            stok[tid] = r;
            swt[tid]  = 1.f;
        }
    }
    __syncthreads();

    float cg[4][2][4], cu[4][2][4];
    #pragma unroll
    for (int mt = 0; mt < 4; mt++)
        #pragma unroll
        for (int nt = 0; nt < 2; nt++)
            #pragma unroll
            for (int j = 0; j < 4; j++) { cg[mt][nt][j] = 0.f; cu[mt][nt][j] = 0.f; }

    // staging regs: A 2 float4, Bg 1, Bu 1
    const int ar = tid >> 2, ak = tid & 3;       // A row (with +64), k-quad
    const int br = tid >> 2, bk = tid & 3;       // B row, k-quad
    float4 ra0, ra1, rg0, ru0;

    auto ldg_chunk = [&](int c) {
        int k0 = c * BK;
        ra0 = *(const float4*)(X + (size_t)stok[ar]      * H_ + k0 + ak * 4);
        ra1 = *(const float4*)(X + (size_t)stok[ar + 64] * H_ + k0 + ak * 4);
        rg0 = *(const float4*)(wg + (size_t)(n0 + br) * H_ + k0 + bk * 4);
        ru0 = *(const float4*)(wu + (size_t)(n0 + br) * H_ + k0 + bk * 4);
    };
    auto sts_chunk = [&](int b) {
        *(uint4*)&As[b][ar     ][ak * 4] = tf32x4(ra0);
        *(uint4*)&As[b][ar + 64][ak * 4] = tf32x4(ra1);
        *(uint4*)&Bg[b][br][bk * 4] = tf32x4(rg0);
        *(uint4*)&Bu[b][br][bk * 4] = tf32x4(ru0);
    };

    ldg_chunk(0);
    for (int c = 0; c < NC; c++) {
        const int b = c & 1;
        sts_chunk(b);
        __syncthreads();
        if (c + 1 < NC) ldg_chunk(c + 1);

        #pragma unroll
        for (int ks = 0; ks < 2; ks++) {
            uint32_t af[4][4];
            #pragma unroll
            for (int mt = 0; mt < 4; mt++) {
                int rm = wm * 64 + mt * 16;
                af[mt][0] = FB(As[b][rm + gp    ][ks * 8 + tg]);
                af[mt][1] = FB(As[b][rm + gp + 8][ks * 8 + tg]);
                af[mt][2] = FB(As[b][rm + gp    ][ks * 8 + tg + 4]);
                af[mt][3] = FB(As[b][rm + gp + 8][ks * 8 + tg + 4]);
            }
            uint32_t bgf[2][2], buf2[2][2];
            #pragma unroll
            for (int nt = 0; nt < 2; nt++) {
                int rn = wn * 16 + nt * 8;
                bgf[nt][0]  = FB(Bg[b][rn + gp][ks * 8 + tg]);
                bgf[nt][1]  = FB(Bg[b][rn + gp][ks * 8 + tg + 4]);
                buf2[nt][0] = FB(Bu[b][rn + gp][ks * 8 + tg]);
                buf2[nt][1] = FB(Bu[b][rn + gp][ks * 8 + tg + 4]);
            }
            #pragma unroll
            for (int mt = 0; mt < 4; mt++)
                #pragma unroll
                for (int nt = 0; nt < 2; nt++) {
                    mma8(cg[mt][nt], af[mt], bgf[nt]);
                    mma8(cu[mt][nt], af[mt], buf2[nt]);
                }
        }
        __syncthreads();
    }

    // Epilogue: SwiGLU, fold combine weight, store activations
    #pragma unroll
    for (int mt = 0; mt < 4; mt++) {
        int r0 = wm * 64 + mt * 16 + gp;
        int r1 = r0 + 8;
        #pragma unroll
        for (int nt = 0; nt < 2; nt++) {
            int col = n0 + wn * 16 + nt * 8 + tg * 2;
            if (m0 + r0 < ne) {
                float w = swt[r0];
                float2 o;
                o.x = siluf(cg[mt][nt][0]) * cu[mt][nt][0] * w;
                o.y = siluf(cg[mt][nt][1]) * cu[mt][nt][1] * w;
                *(float2*)(aout + (size_t)(m0 + r0) * NTOT + col) = o;
            }
            if (m0 + r1 < ne) {
                float w = swt[r1];
                float2 o;
                o.x = siluf(cg[mt][nt][2]) * cu[mt][nt][2] * w;
                o.y = siluf(cg[mt][nt][3]) * cu[mt][nt][3] * w;
                *(float2*)(aout + (size_t)(m0 + r1) * NTOT + col) = o;
            }
        }
    }
}

// ---------------------------------------------------------------------------
// Kernel 3: down projection — tf32 mma.sync GEMM.
// Block tile (MT*32)(M) x 128(N), BK=16. MT=4 routed (atomicAdd scatter),
// MT=2 shared (plain store, initializes Y; 128 blocks for chip fill).
// ---------------------------------------------------------------------------
template<bool ROUTED, int KD, int MT>
__global__ void __launch_bounds__(256, 2) down_tc(
    const float* __restrict__ Wd,
    float* __restrict__ Y)
{
    constexpr int BK = 16, NC = KD / BK, SK = 20, BM = MT * 32;

    const int e  = ROUTED ? blockIdx.z : 0;
    const int ne = ROUTED ? g_cnt[e] : T_;
    const int m0 = blockIdx.y * BM;
    if (m0 >= ne) return;
    const int n0 = blockIdx.x * 128;

    __shared__ __align__(16) float As[2][BM][SK];
    __shared__ __align__(16) float Bs[2][128][SK];
    __shared__ int stok[BM];

    const float* A = ROUTED ? (g_act + (size_t)e * T_ * KD) : g_shact;
    const float* W = Wd + (ROUTED ? (size_t)e * H_ * KD : 0);

    const int tid = threadIdx.x, wid = tid >> 5, lid = tid & 31;
    const int wm = wid & 1, wn = wid >> 1;
    const int gp = lid >> 2, tg = lid & 3;

    if (tid < BM) {
        int r = m0 + tid;
        stok[tid] = ROUTED ? ((r < ne) ? g_tok[e * T_ + r] : 0) : r;
    }
    __syncthreads();

    float cc[MT][4][4];
    #pragma unroll
    for (int mt = 0; mt < MT; mt++)
        #pragma unroll
        for (int nt = 0; nt < 4; nt++)
            #pragma unroll
            for (int j = 0; j < 4; j++) cc[mt][nt][j] = 0.f;

    const int ar = tid >> 2, ak = tid & 3;
    float4 ra[MT / 2], rb0, rb1;

    auto ldg_chunk = [&](int c) {
        int k0 = c * BK;
        #pragma unroll
        for (int q = 0; q < MT / 2; q++)
            ra[q] = *(const float4*)(A + (size_t)(m0 + ar + q * 64) * KD + k0 + ak * 4);
        rb0 = *(const float4*)(W + (size_t)(n0 + ar)      * KD + k0 + ak * 4);
        rb1 = *(const float4*)(W + (size_t)(n0 + ar + 64) * KD + k0 + ak * 4);
    };
    auto sts_chunk = [&](int b) {
        #pragma unroll
        for (int q = 0; q < MT / 2; q++)
            *(uint4*)&As[b][ar + q * 64][ak * 4] = tf32x4(ra[q]);
        *(uint4*)&Bs[b][ar     ][ak * 4] = tf32x4(rb0);
        *(uint4*)&Bs[b][ar + 64][ak * 4] = tf32x4(rb1);
    };

    ldg_chunk(0);
    for (int c = 0; c < NC; c++) {
        const int b = c & 1;
        sts_chunk(b);
        __syncthreads();
        if (c + 1 < NC) ldg_chunk(c + 1);

        #pragma unroll
        for (int ks = 0; ks < 2; ks++) {
            uint32_t af[MT][4];
            #pragma unroll
            for (int mt = 0; mt < MT; mt++) {
                int rm = wm * (MT * 16) + mt * 16;
                af[mt][0] = FB(As[b][rm + gp    ][ks * 8 + tg]);
                af[mt][1] = FB(As[b][rm + gp + 8][ks * 8 + tg]);
                af[mt][2] = FB(As[b][rm + gp    ][ks * 8 + tg + 4]);
                af[mt][3] = FB(As[b][rm + gp + 8][ks * 8 + tg + 4]);
            }
            uint32_t bf[4][2];
            #pragma unroll
            for (int nt = 0; nt < 4; nt++) {
                int rn = wn * 32 + nt * 8;
                bf[nt][0] = FB(Bs[b][rn + gp][ks * 8 + tg]);
                bf[nt][1] = FB(Bs[b][rn + gp][ks * 8 + tg + 4]);
            }
            #pragma unroll
            for (int mt = 0; mt < MT; mt++)
                #pragma unroll
                for (int nt = 0; nt < 4; nt++)
                    mma8(cc[mt][nt], af[mt], bf[nt]);
        }
        __syncthreads();
    }

    // Epilogue
    #pragma unroll
    for (int mt = 0; mt < MT; mt++) {
        int r0 = wm * (MT * 16) + mt * 16 + gp;
        int r1 = r0 + 8;
        #pragma unroll
        for (int nt = 0; nt < 4; nt++) {
            int col = n0 + wn * 32 + nt * 8 + tg * 2;
            if (ROUTED) {
                if (m0 + r0 < ne) {
                    float* yr = Y + (size_t)stok[r0] * H_ + col;
                    atomicAdd(yr,     cc[mt][nt][0]);
                    atomicAdd(yr + 1, cc[mt][nt][1]);
                }
                if (m0 + r1 < ne) {
                    float* yr = Y + (size_t)stok[r1] * H_ + col;
                    atomicAdd(yr,     cc[mt][nt][2]);
                    atomicAdd(yr + 1, cc[mt][nt][3]);
                }
            } else {
                float2 o0 = make_float2(cc[mt][nt][0], cc[mt][nt][1]);
                float2 o1 = make_float2(cc[mt][nt][2], cc[mt][nt][3]);
                *(float2*)(Y + (size_t)(m0 + r0) * H_ + col) = o0;
                *(float2*)(Y + (size_t)(m0 + r1) * H_ + col) = o1;
            }
        }
    }
}

// ---------------------------------------------------------------------------
// Launch sequence (default stream; graph-capturable: kernel launches only)
// ---------------------------------------------------------------------------
extern "C" void kernel_launch(void* const* d_in, const int* in_sizes, int n_in,
                              void* d_out, int out_size) {
    (void)in_sizes; (void)n_in; (void)out_size;
    const float* x   = (const float*)d_in[0];
    const float* gw  = (const float*)d_in[1];
    const float* gb  = (const float*)d_in[2];
    const float* gp  = (const float*)d_in[3];
    const float* up  = (const float*)d_in[4];
    const float* dp  = (const float*)d_in[5];
    const float* sgw = (const float*)d_in[6];
    const float* suw = (const float*)d_in[7];
    const float* sdw = (const float*)d_in[8];
    float* y = (float*)d_out;

    zero_cnt_kernel<<<1, 32>>>();
    gate_kernel<<<T_, 128>>>(x, gw, gb);

    // activations (shared first so both MLP1s overlap-fill the machine)
    mlp1_tc<false, IS_><<<dim3(IS_ / 64, T_ / 128),     256>>>(x, sgw, suw);
    mlp1_tc<true,  I_ ><<<dim3(I_  / 64, T_ / 128, E_), 256>>>(x, gp,  up);

    // down: shared writes Y (init), routed accumulates on top
    down_tc<false, IS_, 2><<<dim3(H_ / 128, T_ / 64),      256>>>(sdw, y);
    down_tc<true,  I_,  4><<<dim3(H_ / 128, T_ / 128, E_), 256>>>(dp,  y);
}

// round 13
// speedup vs baseline: 1.0852x; 1.0852x over previous
#include <cuda_runtime.h>
#include <cstdint>
#include <math.h>

// Problem constants
#define T_  1024
#define H_  1024
#define E_  16
#define K_  4
#define I_  1408
#define IS_ 2816

// ---------------------------------------------------------------------------
// Device scratch (static globals — no runtime allocation allowed)
// ---------------------------------------------------------------------------
__device__ int   g_cnt[E_];                       // tokens per expert
__device__ int   g_tok[E_ * T_];                  // per-expert token lists
__device__ float g_wt [E_ * T_];                  // per-assignment combine weight
__device__ float g_act[(size_t)E_ * T_ * I_];     // routed SwiGLU acts (weight-folded)
__device__ float g_shact[(size_t)T_ * IS_];       // shared-expert activations

// ---------------------------------------------------------------------------
// Helpers
// ---------------------------------------------------------------------------
__device__ __forceinline__ float siluf(float g) { return g / (1.f + __expf(-g)); }

__device__ __forceinline__ uint32_t smem_u32(const void* p) {
    uint32_t a;
    asm("{ .reg .u64 t; cvta.to.shared.u64 t, %1; cvt.u32.u64 %0, t; }"
        : "=r"(a) : "l"(p));
    return a;
}

// tf32 round (rna) of a float4, raw bits
__device__ __forceinline__ uint4 tf32x4(float4 v) {
    uint4 u;
    asm("cvt.rna.tf32.f32 %0, %1;" : "=r"(u.x) : "f"(v.x));
    asm("cvt.rna.tf32.f32 %0, %1;" : "=r"(u.y) : "f"(v.y));
    asm("cvt.rna.tf32.f32 %0, %1;" : "=r"(u.z) : "f"(v.z));
    asm("cvt.rna.tf32.f32 %0, %1;" : "=r"(u.w) : "f"(v.w));
    return u;
}

// m16n8k8 tf32 MMA, D += A*B (fp32 accum in regs)
__device__ __forceinline__ void mma8(float* d, const uint32_t* a, const uint32_t* b) {
    asm volatile(
        "mma.sync.aligned.m16n8k8.row.col.f32.tf32.tf32.f32 "
        "{%0,%1,%2,%3}, {%4,%5,%6,%7}, {%8,%9}, {%0,%1,%2,%3};"
        : "+f"(d[0]), "+f"(d[1]), "+f"(d[2]), "+f"(d[3])
        : "r"(a[0]), "r"(a[1]), "r"(a[2]), "r"(a[3]), "r"(b[0]), "r"(b[1]));
}

// ldmatrix x4: 4 8x8 b16 matrices (type-agnostic bit movement; sm_75+ PTX, so
// it assembles on the compute_103 virtual arch unlike tcgen05.*)
__device__ __forceinline__ void ldsm4(uint32_t* r, uint32_t addr) {
    asm volatile("ldmatrix.sync.aligned.m8n8.x4.shared.b16 {%0,%1,%2,%3}, [%4];"
                 : "=r"(r[0]), "=r"(r[1]), "=r"(r[2]), "=r"(r[3]) : "r"(addr));
}

// ---------------------------------------------------------------------------
// Kernel 0: reset per-expert counters
// ---------------------------------------------------------------------------
__global__ void zero_cnt_kernel() {
    if (threadIdx.x < E_) g_cnt[threadIdx.x] = 0;
}

// ---------------------------------------------------------------------------
// Kernel 1: gating (exact fp32 — routing must match the reference bit-wise)
// ---------------------------------------------------------------------------
__global__ void __launch_bounds__(128) gate_kernel(
    const float* __restrict__ X,
    const float* __restrict__ GW,
    const float* __restrict__ GB)
{
    __shared__ float xs[H_];
    __shared__ float sl[E_];
    const int t = blockIdx.x;
    const int tid = threadIdx.x;

    #pragma unroll
    for (int q = 0; q < 2; q++) {
        int i = (tid + q * 128) * 4;
        *(float4*)&xs[i] = *(const float4*)(X + (size_t)t * H_ + i);
    }
    __syncthreads();

    const int warp = tid >> 5, lane = tid & 31;
    #pragma unroll
    for (int sub = 0; sub < 4; sub++) {
        int e = warp * 4 + sub;
        const float* w = GW + (size_t)e * H_;
        float s = 0.f;
        for (int k = lane * 4; k < H_; k += 128) {
            float4 xv = *(const float4*)&xs[k];
            float4 wv = *(const float4*)(w + k);
            s = fmaf(xv.x, wv.x, s); s = fmaf(xv.y, wv.y, s);
            s = fmaf(xv.z, wv.z, s); s = fmaf(xv.w, wv.w, s);
        }
        #pragma unroll
        for (int o = 16; o > 0; o >>= 1) s += __shfl_xor_sync(0xffffffffu, s, o);
        if (lane == 0) sl[e] = s;
    }
    __syncthreads();

    if (tid == 0) {
        float sc[E_], sfc[E_];
        #pragma unroll
        for (int e = 0; e < E_; e++) {
            sc[e]  = 1.f / (1.f + __expf(-sl[e]));
            sfc[e] = sc[e] + GB[e];
        }
        float gs[4];
        #pragma unroll
        for (int g = 0; g < 4; g++) {
            float m1 = -1e30f, m2 = -1e30f;
            #pragma unroll
            for (int j = 0; j < 4; j++) {
                float v = sfc[g * 4 + j];
                if (v > m1) { m2 = m1; m1 = v; } else if (v > m2) m2 = v;
            }
            gs[g] = m1 + m2;
        }
        int g1 = 0;
        for (int g = 1; g < 4; g++) if (gs[g] > gs[g1]) g1 = g;
        int g2 = -1;
        for (int g = 0; g < 4; g++) {
            if (g == g1) continue;
            if (g2 < 0 || gs[g] > gs[g2]) g2 = g;
        }
        float tmp[E_];
        #pragma unroll
        for (int e = 0; e < E_; e++) {
            int gg = e >> 2;
            tmp[e] = (gg == g1 || gg == g2) ? sfc[e] : 0.f;
        }
        int   idx[K_];
        float wv[K_];
        float wsum = 0.f;
        #pragma unroll
        for (int k = 0; k < K_; k++) {
            int best = 0; float bv = -1e30f;
            #pragma unroll
            for (int e = 0; e < E_; e++) if (tmp[e] > bv) { bv = tmp[e]; best = e; }
            idx[k] = best; wv[k] = sc[best]; wsum += sc[best];
            tmp[best] = -1e30f;
        }
        float inv = 1.f / (wsum + 1e-20f);
        #pragma unroll
        for (int k = 0; k < K_; k++) {
            int e = idx[k];
            int slot = atomicAdd(&g_cnt[e], 1);
            g_tok[e * T_ + slot] = t;
            g_wt [e * T_ + slot] = wv[k] * inv;
        }
    }
}

// ---------------------------------------------------------------------------
// Kernel 2: mlp1 — tf32 mma.sync grouped GEMM, dual-B (gate+up), fused SwiGLU.
// Block tile 128(M) x 64(N per matrix), BK=16, 256 thr (8 warps, 2m x 4n).
// Fragments via ldmatrix.x4; double-buffered smem, ONE barrier per chunk.
// ---------------------------------------------------------------------------
template<bool ROUTED, int NTOT>
__global__ void __launch_bounds__(256, 2) mlp1_tc(
    const float* __restrict__ X,
    const float* __restrict__ Wg,
    const float* __restrict__ Wu)
{
    constexpr int BK = 16, NC = H_ / BK, SK = 20;  // padded stride

    const int e  = ROUTED ? blockIdx.z : 0;
    const int ne = ROUTED ? g_cnt[e] : T_;
    const int m0 = blockIdx.y * 128;
    if (m0 >= ne) return;
    const int n0 = blockIdx.x * 64;

    __shared__ __align__(16) float As[2][128][SK];
    __shared__ __align__(16) float Bg[2][64][SK];
    __shared__ __align__(16) float Bu[2][64][SK];
    __shared__ int   stok[128];
    __shared__ float swt[128];

    const float* wg = Wg + (size_t)e * NTOT * H_;
    const float* wu = Wu + (size_t)e * NTOT * H_;
    float* aout = ROUTED ? (g_act + (size_t)e * T_ * NTOT) : g_shact;

    const int tid = threadIdx.x, wid = tid >> 5, lid = tid & 31;
    const int wm = wid & 1, wn = wid >> 1;
    const int gp = lid >> 2, tg = lid & 3;

    if (tid < 128) {
        int r = m0 + tid;
        if (ROUTED) {
            stok[tid] = (r < ne) ? g_tok[e * T_ + r] : 0;
            swt[tid]  = (r < ne) ? g_wt [e * T_ + r] : 0.f;
        } else {
            stok[tid] = r;
            swt[tid]  = 1.f;
        }
    }
    __syncthreads();

    // ldmatrix per-thread base addresses
    // A matrices: lanes 0-7 rows+0..7/col+0, 8-15 rows+8/col+0, 16-23 rows/col+4, 24-31 rows+8/col+4
    const int ra_row = (((lid >> 3) & 1) << 3) + (lid & 7);
    const int ra_col = (lid >> 4) << 2;
    // B matrices: m0 rows+0 col+0 (nt0 b0), m1 rows+0 col+4 (nt0 b1), m2 rows+8 col+0, m3 rows+8 col+4
    const int rb_row = (((lid >> 4) & 1) << 3) + (lid & 7);
    const int rb_col = ((lid >> 3) & 1) << 2;

    const uint32_t aA = smem_u32(&As[0][0][0]) + ((wm * 64 + ra_row) * SK + ra_col) * 4;
    const uint32_t aG = smem_u32(&Bg[0][0][0]) + ((wn * 16 + rb_row) * SK + rb_col) * 4;
    const uint32_t aU = smem_u32(&Bu[0][0][0]) + ((wn * 16 + rb_row) * SK + rb_col) * 4;
    constexpr uint32_t ABUF = 128 * SK * 4, BBUF = 64 * SK * 4;

    float cg[4][2][4], cu[4][2][4];
    #pragma unroll
    for (int mt = 0; mt < 4; mt++)
        #pragma unroll
        for (int nt = 0; nt < 2; nt++)
            #pragma unroll
            for (int j = 0; j < 4; j++) { cg[mt][nt][j] = 0.f; cu[mt][nt][j] = 0.f; }

    const int ar = tid >> 2, ak = tid & 3;
    float4 ra0, ra1, rg0, ru0;

    auto ldg_chunk = [&](int c) {
        int k0 = c * BK;
        ra0 = *(const float4*)(X + (size_t)stok[ar]      * H_ + k0 + ak * 4);
        ra1 = *(const float4*)(X + (size_t)stok[ar + 64] * H_ + k0 + ak * 4);
        rg0 = *(const float4*)(wg + (size_t)(n0 + ar) * H_ + k0 + ak * 4);
        ru0 = *(const float4*)(wu + (size_t)(n0 + ar) * H_ + k0 + ak * 4);
    };
    auto sts_chunk = [&](int b) {
        *(uint4*)&As[b][ar     ][ak * 4] = tf32x4(ra0);
        *(uint4*)&As[b][ar + 64][ak * 4] = tf32x4(ra1);
        *(uint4*)&Bg[b][ar][ak * 4] = tf32x4(rg0);
        *(uint4*)&Bu[b][ar][ak * 4] = tf32x4(ru0);
    };

    ldg_chunk(0);
    for (int c = 0; c < NC; c++) {
        const int b = c & 1;
        sts_chunk(b);
        __syncthreads();                 // single barrier per chunk
        if (c + 1 < NC) ldg_chunk(c + 1);

        const uint32_t oA = aA + b * ABUF;
        const uint32_t oG = aG + b * BBUF;
        const uint32_t oU = aU + b * BBUF;
        #pragma unroll
        for (int ks = 0; ks < 2; ks++) {
            uint32_t af[4][4], bgf[4], buf2[4];
            #pragma unroll
            for (int mt = 0; mt < 4; mt++)
                ldsm4(af[mt], oA + mt * (16 * SK * 4) + ks * 32);
            ldsm4(bgf,  oG + ks * 32);   // {nt0.b0, nt0.b1, nt1.b0, nt1.b1}
            ldsm4(buf2, oU + ks * 32);
            #pragma unroll
            for (int mt = 0; mt < 4; mt++)
                #pragma unroll
                for (int nt = 0; nt < 2; nt++) {
                    mma8(cg[mt][nt], af[mt], &bgf[nt * 2]);
                    mma8(cu[mt][nt], af[mt], &buf2[nt * 2]);
                }
        }
    }

    // Epilogue: SwiGLU, fold combine weight, store activations
    #pragma unroll
    for (int mt = 0; mt < 4; mt++) {
        int r0 = wm * 64 + mt * 16 + gp;
        int r1 = r0 + 8;
        #pragma unroll
        for (int nt = 0; nt < 2; nt++) {
            int col = n0 + wn * 16 + nt * 8 + tg * 2;
            if (m0 + r0 < ne) {
                float w = swt[r0];
                float2 o;
                o.x = siluf(cg[mt][nt][0]) * cu[mt][nt][0] * w;
                o.y = siluf(cg[mt][nt][1]) * cu[mt][nt][1] * w;
                *(float2*)(aout + (size_t)(m0 + r0) * NTOT + col) = o;
            }
            if (m0 + r1 < ne) {
                float w = swt[r1];
                float2 o;
                o.x = siluf(cg[mt][nt][2]) * cu[mt][nt][2] * w;
                o.y = siluf(cg[mt][nt][3]) * cu[mt][nt][3] * w;
                *(float2*)(aout + (size_t)(m0 + r1) * NTOT + col) = o;
            }
        }
    }
}

// ---------------------------------------------------------------------------
// Kernel 3: down projection — tf32 mma.sync GEMM with ldmatrix fragments.
// Block tile (MT*32)(M) x 128(N), BK=16. MT=4 routed (atomicAdd scatter),
// MT=2 shared (plain store, initializes Y).
// ---------------------------------------------------------------------------
template<bool ROUTED, int KD, int MT>
__global__ void __launch_bounds__(256, 2) down_tc(
    const float* __restrict__ Wd,
    float* __restrict__ Y)
{
    constexpr int BK = 16, NC = KD / BK, SK = 20, BM = MT * 32;

    const int e  = ROUTED ? blockIdx.z : 0;
    const int ne = ROUTED ? g_cnt[e] : T_;
    const int m0 = blockIdx.y * BM;
    if (m0 >= ne) return;
    const int n0 = blockIdx.x * 128;

    __shared__ __align__(16) float As[2][BM][SK];
    __shared__ __align__(16) float Bs[2][128][SK];
    __shared__ int stok[BM];

    const float* A = ROUTED ? (g_act + (size_t)e * T_ * KD) : g_shact;
    const float* W = Wd + (ROUTED ? (size_t)e * H_ * KD : 0);

    const int tid = threadIdx.x, wid = tid >> 5, lid = tid & 31;
    const int wm = wid & 1, wn = wid >> 1;
    const int gp = lid >> 2, tg = lid & 3;

    if (tid < BM) {
        int r = m0 + tid;
        stok[tid] = ROUTED ? ((r < ne) ? g_tok[e * T_ + r] : 0) : r;
    }
    __syncthreads();

    const int ra_row = (((lid >> 3) & 1) << 3) + (lid & 7);
    const int ra_col = (lid >> 4) << 2;
    const int rb_row = (((lid >> 4) & 1) << 3) + (lid & 7);
    const int rb_col = ((lid >> 3) & 1) << 2;

    const uint32_t aA = smem_u32(&As[0][0][0]) + ((wm * (MT * 16) + ra_row) * SK + ra_col) * 4;
    const uint32_t aB = smem_u32(&Bs[0][0][0]) + ((wn * 32 + rb_row) * SK + rb_col) * 4;
    constexpr uint32_t ABUF = BM * SK * 4, BBUF = 128 * SK * 4;

    float cc[MT][4][4];
    #pragma unroll
    for (int mt = 0; mt < MT; mt++)
        #pragma unroll
        for (int nt = 0; nt < 4; nt++)
            #pragma unroll
            for (int j = 0; j < 4; j++) cc[mt][nt][j] = 0.f;

    const int ar = tid >> 2, ak = tid & 3;
    float4 ra[MT / 2], rb0, rb1;

    auto ldg_chunk = [&](int c) {
        int k0 = c * BK;
        #pragma unroll
        for (int q = 0; q < MT / 2; q++)
            ra[q] = *(const float4*)(A + (size_t)(m0 + ar + q * 64) * KD + k0 + ak * 4);
        rb0 = *(const float4*)(W + (size_t)(n0 + ar)      * KD + k0 + ak * 4);
        rb1 = *(const float4*)(W + (size_t)(n0 + ar + 64) * KD + k0 + ak * 4);
    };
    auto sts_chunk = [&](int b) {
        #pragma unroll
        for (int q = 0; q < MT / 2; q++)
            *(uint4*)&As[b][ar + q * 64][ak * 4] = tf32x4(ra[q]);
        *(uint4*)&Bs[b][ar     ][ak * 4] = tf32x4(rb0);
        *(uint4*)&Bs[b][ar + 64][ak * 4] = tf32x4(rb1);
    };

    ldg_chunk(0);
    for (int c = 0; c < NC; c++) {
        const int b = c & 1;
        sts_chunk(b);
        __syncthreads();                 // single barrier per chunk
        if (c + 1 < NC) ldg_chunk(c + 1);

        const uint32_t oA = aA + b * ABUF;
        const uint32_t oB = aB + b * BBUF;
        #pragma unroll
        for (int ks = 0; ks < 2; ks++) {
            uint32_t af[MT][4];
            #pragma unroll
            for (int mt = 0; mt < MT; mt++)
                ldsm4(af[mt], oA + mt * (16 * SK * 4) + ks * 32);
            uint32_t bf[2][4];           // pair p -> {nt(2p).b0, b1, nt(2p+1).b0, b1}
            #pragma unroll
            for (int p = 0; p < 2; p++)
                ldsm4(bf[p], oB + p * (16 * SK * 4) + ks * 32);
            #pragma unroll
            for (int mt = 0; mt < MT; mt++)
                #pragma unroll
                for (int nt = 0; nt < 4; nt++)
                    mma8(cc[mt][nt], af[mt], &bf[nt >> 1][(nt & 1) * 2]);
        }
    }

    // Epilogue
    #pragma unroll
    for (int mt = 0; mt < MT; mt++) {
        int r0 = wm * (MT * 16) + mt * 16 + gp;
        int r1 = r0 + 8;
        #pragma unroll
        for (int nt = 0; nt < 4; nt++) {
            int col = n0 + wn * 32 + nt * 8 + tg * 2;
            if (ROUTED) {
                if (m0 + r0 < ne) {
                    float* yr = Y + (size_t)stok[r0] * H_ + col;
                    atomicAdd(yr,     cc[mt][nt][0]);
                    atomicAdd(yr + 1, cc[mt][nt][1]);
                }
                if (m0 + r1 < ne) {
                    float* yr = Y + (size_t)stok[r1] * H_ + col;
                    atomicAdd(yr,     cc[mt][nt][2]);
                    atomicAdd(yr + 1, cc[mt][nt][3]);
                }
            } else {
                float2 o0 = make_float2(cc[mt][nt][0], cc[mt][nt][1]);
                float2 o1 = make_float2(cc[mt][nt][2], cc[mt][nt][3]);
                *(float2*)(Y + (size_t)(m0 + r0) * H_ + col) = o0;
                *(float2*)(Y + (size_t)(m0 + r1) * H_ + col) = o1;
            }
        }
    }
}

// ---------------------------------------------------------------------------
// Launch sequence (default stream; graph-capturable: kernel launches only)
// ---------------------------------------------------------------------------
extern "C" void kernel_launch(void* const* d_in, const int* in_sizes, int n_in,
                              void* d_out, int out_size) {
    (void)in_sizes; (void)n_in; (void)out_size;
    const float* x   = (const float*)d_in[0];
    const float* gw  = (const float*)d_in[1];
    const float* gb  = (const float*)d_in[2];
    const float* gp  = (const float*)d_in[3];
    const float* up  = (const float*)d_in[4];
    const float* dp  = (const float*)d_in[5];
    const float* sgw = (const float*)d_in[6];
    const float* suw = (const float*)d_in[7];
    const float* sdw = (const float*)d_in[8];
    float* y = (float*)d_out;

    zero_cnt_kernel<<<1, 32>>>();
    gate_kernel<<<T_, 128>>>(x, gw, gb);

    // activations
    mlp1_tc<false, IS_><<<dim3(IS_ / 64, T_ / 128),     256>>>(x, sgw, suw);
    mlp1_tc<true,  I_ ><<<dim3(I_  / 64, T_ / 128, E_), 256>>>(x, gp,  up);

    // down: shared writes Y (init), routed accumulates on top
    down_tc<false, IS_, 2><<<dim3(H_ / 128, T_ / 64),      256>>>(sdw, y);
    down_tc<true,  I_,  4><<<dim3(H_ / 128, T_ / 128, E_), 256>>>(dp,  y);
}

// round 14
// speedup vs baseline: 1.1137x; 1.0262x over previous
#include <cuda_runtime.h>
#include <cstdint>
#include <math.h>

// Problem constants
#define T_  1024
#define H_  1024
#define E_  16
#define K_  4
#define I_  1408
#define IS_ 2816

// ---------------------------------------------------------------------------
// Device scratch (static globals — no runtime allocation allowed)
// ---------------------------------------------------------------------------
__device__ int   g_cnt[E_];                       // tokens per expert
__device__ int   g_tok[E_ * T_];                  // per-expert token lists
__device__ float g_wt [E_ * T_];                  // per-assignment combine weight
__device__ float g_act[(size_t)E_ * T_ * I_];     // routed SwiGLU acts (weight-folded)
__device__ float g_shact[(size_t)T_ * IS_];       // shared-expert activations

// ---------------------------------------------------------------------------
// Helpers
// ---------------------------------------------------------------------------
__device__ __forceinline__ float siluf(float g) { return g / (1.f + __expf(-g)); }

__device__ __forceinline__ uint32_t smem_u32(const void* p) {
    uint32_t a;
    asm("{ .reg .u64 t; cvta.to.shared.u64 t, %1; cvt.u32.u64 %0, t; }"
        : "=r"(a) : "l"(p));
    return a;
}

// tf32 round (rna) of a float4, raw bits
__device__ __forceinline__ uint4 tf32x4(float4 v) {
    uint4 u;
    asm("cvt.rna.tf32.f32 %0, %1;" : "=r"(u.x) : "f"(v.x));
    asm("cvt.rna.tf32.f32 %0, %1;" : "=r"(u.y) : "f"(v.y));
    asm("cvt.rna.tf32.f32 %0, %1;" : "=r"(u.z) : "f"(v.z));
    asm("cvt.rna.tf32.f32 %0, %1;" : "=r"(u.w) : "f"(v.w));
    return u;
}

// m16n8k8 tf32 MMA, D += A*B (fp32 accum in regs)
__device__ __forceinline__ void mma8(float* d, const uint32_t* a, const uint32_t* b) {
    asm volatile(
        "mma.sync.aligned.m16n8k8.row.col.f32.tf32.tf32.f32 "
        "{%0,%1,%2,%3}, {%4,%5,%6,%7}, {%8,%9}, {%0,%1,%2,%3};"
        : "+f"(d[0]), "+f"(d[1]), "+f"(d[2]), "+f"(d[3])
        : "r"(a[0]), "r"(a[1]), "r"(a[2]), "r"(a[3]), "r"(b[0]), "r"(b[1]));
}

// ldmatrix x4: 4 8x8 b16 matrices (type-agnostic bit movement; sm_75+ PTX, so
// it assembles on the compute_103 virtual arch unlike tcgen05.*)
__device__ __forceinline__ void ldsm4(uint32_t* r, uint32_t addr) {
    asm volatile("ldmatrix.sync.aligned.m8n8.x4.shared.b16 {%0,%1,%2,%3}, [%4];"
                 : "=r"(r[0]), "=r"(r[1]), "=r"(r[2]), "=r"(r[3]) : "r"(addr));
}

// ---------------------------------------------------------------------------
// Kernel 0: reset per-expert counters
// ---------------------------------------------------------------------------
__global__ void zero_cnt_kernel() {
    if (threadIdx.x < E_) g_cnt[threadIdx.x] = 0;
}

// ---------------------------------------------------------------------------
// Kernel 1: gating (exact fp32 — routing must match the reference bit-wise)
// ---------------------------------------------------------------------------
__global__ void __launch_bounds__(128) gate_kernel(
    const float* __restrict__ X,
    const float* __restrict__ GW,
    const float* __restrict__ GB)
{
    __shared__ float xs[H_];
    __shared__ float sl[E_];
    const int t = blockIdx.x;
    const int tid = threadIdx.x;

    #pragma unroll
    for (int q = 0; q < 2; q++) {
        int i = (tid + q * 128) * 4;
        *(float4*)&xs[i] = *(const float4*)(X + (size_t)t * H_ + i);
    }
    __syncthreads();

    const int warp = tid >> 5, lane = tid & 31;
    #pragma unroll
    for (int sub = 0; sub < 4; sub++) {
        int e = warp * 4 + sub;
        const float* w = GW + (size_t)e * H_;
        float s = 0.f;
        for (int k = lane * 4; k < H_; k += 128) {
            float4 xv = *(const float4*)&xs[k];
            float4 wv = *(const float4*)(w + k);
            s = fmaf(xv.x, wv.x, s); s = fmaf(xv.y, wv.y, s);
            s = fmaf(xv.z, wv.z, s); s = fmaf(xv.w, wv.w, s);
        }
        #pragma unroll
        for (int o = 16; o > 0; o >>= 1) s += __shfl_xor_sync(0xffffffffu, s, o);
        if (lane == 0) sl[e] = s;
    }
    __syncthreads();

    if (tid == 0) {
        float sc[E_], sfc[E_];
        #pragma unroll
        for (int e = 0; e < E_; e++) {
            sc[e]  = 1.f / (1.f + __expf(-sl[e]));
            sfc[e] = sc[e] + GB[e];
        }
        float gs[4];
        #pragma unroll
        for (int g = 0; g < 4; g++) {
            float m1 = -1e30f, m2 = -1e30f;
            #pragma unroll
            for (int j = 0; j < 4; j++) {
                float v = sfc[g * 4 + j];
                if (v > m1) { m2 = m1; m1 = v; } else if (v > m2) m2 = v;
            }
            gs[g] = m1 + m2;
        }
        int g1 = 0;
        for (int g = 1; g < 4; g++) if (gs[g] > gs[g1]) g1 = g;
        int g2 = -1;
        for (int g = 0; g < 4; g++) {
            if (g == g1) continue;
            if (g2 < 0 || gs[g] > gs[g2]) g2 = g;
        }
        float tmp[E_];
        #pragma unroll
        for (int e = 0; e < E_; e++) {
            int gg = e >> 2;
            tmp[e] = (gg == g1 || gg == g2) ? sfc[e] : 0.f;
        }
        int   idx[K_];
        float wv[K_];
        float wsum = 0.f;
        #pragma unroll
        for (int k = 0; k < K_; k++) {
            int best = 0; float bv = -1e30f;
            #pragma unroll
            for (int e = 0; e < E_; e++) if (tmp[e] > bv) { bv = tmp[e]; best = e; }
            idx[k] = best; wv[k] = sc[best]; wsum += sc[best];
            tmp[best] = -1e30f;
        }
        float inv = 1.f / (wsum + 1e-20f);
        #pragma unroll
        for (int k = 0; k < K_; k++) {
            int e = idx[k];
            int slot = atomicAdd(&g_cnt[e], 1);
            g_tok[e * T_ + slot] = t;
            g_wt [e * T_ + slot] = wv[k] * inv;
        }
    }
}

// ---------------------------------------------------------------------------
// Kernel 2: mlp1 — tf32 mma.sync grouped GEMM, dual-B (gate+up), fused SwiGLU.
// Block tile 128(M) x 64(N per matrix), BK=16, 256 thr (8 warps, 2m x 4n).
// Fragments via ldmatrix.x4; double-buffered smem, ONE barrier per chunk.
// ---------------------------------------------------------------------------
template<bool ROUTED, int NTOT>
__global__ void __launch_bounds__(256, 2) mlp1_tc(
    const float* __restrict__ X,
    const float* __restrict__ Wg,
    const float* __restrict__ Wu)
{
    constexpr int BK = 16, NC = H_ / BK, SK = 20;  // padded stride

    const int e  = ROUTED ? blockIdx.z : 0;
    const int ne = ROUTED ? g_cnt[e] : T_;
    const int m0 = blockIdx.y * 128;
    if (m0 >= ne) return;
    const int n0 = blockIdx.x * 64;

    __shared__ __align__(16) float As[2][128][SK];
    __shared__ __align__(16) float Bg[2][64][SK];
    __shared__ __align__(16) float Bu[2][64][SK];
    __shared__ int   stok[128];
    __shared__ float swt[128];

    const float* wg = Wg + (size_t)e * NTOT * H_;
    const float* wu = Wu + (size_t)e * NTOT * H_;
    float* aout = ROUTED ? (g_act + (size_t)e * T_ * NTOT) : g_shact;

    const int tid = threadIdx.x, wid = tid >> 5, lid = tid & 31;
    const int wm = wid & 1, wn = wid >> 1;
    const int gp = lid >> 2, tg = lid & 3;

    if (tid < 128) {
        int r = m0 + tid;
        if (ROUTED) {
            stok[tid] = (r < ne) ? g_tok[e * T_ + r] : 0;
            swt[tid]  = (r < ne) ? g_wt [e * T_ + r] : 0.f;
        } else {
            stok[tid] = r;
            swt[tid]  = 1.f;
        }
    }
    __syncthreads();

    // ldmatrix per-thread base addresses
    // A matrices: lanes 0-7 rows+0..7/col+0, 8-15 rows+8/col+0, 16-23 rows/col+4, 24-31 rows+8/col+4
    const int ra_row = (((lid >> 3) & 1) << 3) + (lid & 7);
    const int ra_col = (lid >> 4) << 2;
    // B matrices: m0 rows+0 col+0 (nt0 b0), m1 rows+0 col+4 (nt0 b1), m2 rows+8 col+0, m3 rows+8 col+4
    const int rb_row = (((lid >> 4) & 1) << 3) + (lid & 7);
    const int rb_col = ((lid >> 3) & 1) << 2;

    const uint32_t aA = smem_u32(&As[0][0][0]) + ((wm * 64 + ra_row) * SK + ra_col) * 4;
    const uint32_t aG = smem_u32(&Bg[0][0][0]) + ((wn * 16 + rb_row) * SK + rb_col) * 4;
    const uint32_t aU = smem_u32(&Bu[0][0][0]) + ((wn * 16 + rb_row) * SK + rb_col) * 4;
    constexpr uint32_t ABUF = 128 * SK * 4, BBUF = 64 * SK * 4;

    float cg[4][2][4], cu[4][2][4];
    #pragma unroll
    for (int mt = 0; mt < 4; mt++)
        #pragma unroll
        for (int nt = 0; nt < 2; nt++)
            #pragma unroll
            for (int j = 0; j < 4; j++) { cg[mt][nt][j] = 0.f; cu[mt][nt][j] = 0.f; }

    const int ar = tid >> 2, ak = tid & 3;
    float4 ra0, ra1, rg0, ru0;

    auto ldg_chunk = [&](int c) {
        int k0 = c * BK;
        ra0 = *(const float4*)(X + (size_t)stok[ar]      * H_ + k0 + ak * 4);
        ra1 = *(const float4*)(X + (size_t)stok[ar + 64] * H_ + k0 + ak * 4);
        rg0 = *(const float4*)(wg + (size_t)(n0 + ar) * H_ + k0 + ak * 4);
        ru0 = *(const float4*)(wu + (size_t)(n0 + ar) * H_ + k0 + ak * 4);
    };
    auto sts_chunk = [&](int b) {
        *(uint4*)&As[b][ar     ][ak * 4] = tf32x4(ra0);
        *(uint4*)&As[b][ar + 64][ak * 4] = tf32x4(ra1);
        *(uint4*)&Bg[b][ar][ak * 4] = tf32x4(rg0);
        *(uint4*)&Bu[b][ar][ak * 4] = tf32x4(ru0);
    };

    ldg_chunk(0);
    for (int c = 0; c < NC; c++) {
        const int b = c & 1;
        sts_chunk(b);
        __syncthreads();                 // single barrier per chunk
        if (c + 1 < NC) ldg_chunk(c + 1);

        const uint32_t oA = aA + b * ABUF;
        const uint32_t oG = aG + b * BBUF;
        const uint32_t oU = aU + b * BBUF;
        #pragma unroll
        for (int ks = 0; ks < 2; ks++) {
            uint32_t af[4][4], bgf[4], buf2[4];
            #pragma unroll
            for (int mt = 0; mt < 4; mt++)
                ldsm4(af[mt], oA + mt * (16 * SK * 4) + ks * 32);
            ldsm4(bgf,  oG + ks * 32);   // {nt0.b0, nt0.b1, nt1.b0, nt1.b1}
            ldsm4(buf2, oU + ks * 32);
            #pragma unroll
            for (int mt = 0; mt < 4; mt++)
                #pragma unroll
                for (int nt = 0; nt < 2; nt++) {
                    mma8(cg[mt][nt], af[mt], &bgf[nt * 2]);
                    mma8(cu[mt][nt], af[mt], &buf2[nt * 2]);
                }
        }
    }

    // Epilogue: SwiGLU, fold combine weight, store activations
    #pragma unroll
    for (int mt = 0; mt < 4; mt++) {
        int r0 = wm * 64 + mt * 16 + gp;
        int r1 = r0 + 8;
        #pragma unroll
        for (int nt = 0; nt < 2; nt++) {
            int col = n0 + wn * 16 + nt * 8 + tg * 2;
            if (m0 + r0 < ne) {
                float w = swt[r0];
                float2 o;
                o.x = siluf(cg[mt][nt][0]) * cu[mt][nt][0] * w;
                o.y = siluf(cg[mt][nt][1]) * cu[mt][nt][1] * w;
                *(float2*)(aout + (size_t)(m0 + r0) * NTOT + col) = o;
            }
            if (m0 + r1 < ne) {
                float w = swt[r1];
                float2 o;
                o.x = siluf(cg[mt][nt][2]) * cu[mt][nt][2] * w;
                o.y = siluf(cg[mt][nt][3]) * cu[mt][nt][3] * w;
                *(float2*)(aout + (size_t)(m0 + r1) * NTOT + col) = o;
            }
        }
    }
}

// ---------------------------------------------------------------------------
// Kernel 3: down projection — tf32 mma.sync GEMM with ldmatrix fragments.
// Block tile (MT*32)(M) x 128(N), BK=16. MT=4 routed (atomicAdd scatter),
// MT=2 shared (plain store, initializes Y).
// ---------------------------------------------------------------------------
template<bool ROUTED, int KD, int MT>
__global__ void __launch_bounds__(256, 2) down_tc(
    const float* __restrict__ Wd,
    float* __restrict__ Y)
{
    constexpr int BK = 16, NC = KD / BK, SK = 20, BM = MT * 32;

    const int e  = ROUTED ? blockIdx.z : 0;
    const int ne = ROUTED ? g_cnt[e] : T_;
    const int m0 = blockIdx.y * BM;
    if (m0 >= ne) return;
    const int n0 = blockIdx.x * 128;

    __shared__ __align__(16) float As[2][BM][SK];
    __shared__ __align__(16) float Bs[2][128][SK];
    __shared__ int stok[BM];

    const float* A = ROUTED ? (g_act + (size_t)e * T_ * KD) : g_shact;
    const float* W = Wd + (ROUTED ? (size_t)e * H_ * KD : 0);

    const int tid = threadIdx.x, wid = tid >> 5, lid = tid & 31;
    const int wm = wid & 1, wn = wid >> 1;
    const int gp = lid >> 2, tg = lid & 3;

    if (tid < BM) {
        int r = m0 + tid;
        stok[tid] = ROUTED ? ((r < ne) ? g_tok[e * T_ + r] : 0) : r;
    }
    __syncthreads();

    const int ra_row = (((lid >> 3) & 1) << 3) + (lid & 7);
    const int ra_col = (lid >> 4) << 2;
    const int rb_row = (((lid >> 4) & 1) << 3) + (lid & 7);
    const int rb_col = ((lid >> 3) & 1) << 2;

    const uint32_t aA = smem_u32(&As[0][0][0]) + ((wm * (MT * 16) + ra_row) * SK + ra_col) * 4;
    const uint32_t aB = smem_u32(&Bs[0][0][0]) + ((wn * 32 + rb_row) * SK + rb_col) * 4;
    constexpr uint32_t ABUF = BM * SK * 4, BBUF = 128 * SK * 4;

    float cc[MT][4][4];
    #pragma unroll
    for (int mt = 0; mt < MT; mt++)
        #pragma unroll
        for (int nt = 0; nt < 4; nt++)
            #pragma unroll
            for (int j = 0; j < 4; j++) cc[mt][nt][j] = 0.f;

    const int ar = tid >> 2, ak = tid & 3;
    float4 ra[MT / 2], rb0, rb1;

    auto ldg_chunk = [&](int c) {
        int k0 = c * BK;
        #pragma unroll
        for (int q = 0; q < MT / 2; q++)
            ra[q] = *(const float4*)(A + (size_t)(m0 + ar + q * 64) * KD + k0 + ak * 4);
        rb0 = *(const float4*)(W + (size_t)(n0 + ar)      * KD + k0 + ak * 4);
        rb1 = *(const float4*)(W + (size_t)(n0 + ar + 64) * KD + k0 + ak * 4);
    };
    auto sts_chunk = [&](int b) {
        #pragma unroll
        for (int q = 0; q < MT / 2; q++)
            *(uint4*)&As[b][ar + q * 64][ak * 4] = tf32x4(ra[q]);
        *(uint4*)&Bs[b][ar     ][ak * 4] = tf32x4(rb0);
        *(uint4*)&Bs[b][ar + 64][ak * 4] = tf32x4(rb1);
    };

    ldg_chunk(0);
    for (int c = 0; c < NC; c++) {
        const int b = c & 1;
        sts_chunk(b);
        __syncthreads();                 // single barrier per chunk
        if (c + 1 < NC) ldg_chunk(c + 1);

        const uint32_t oA = aA + b * ABUF;
        const uint32_t oB = aB + b * BBUF;
        #pragma unroll
        for (int ks = 0; ks < 2; ks++) {
            uint32_t af[MT][4];
            #pragma unroll
            for (int mt = 0; mt < MT; mt++)
                ldsm4(af[mt], oA + mt * (16 * SK * 4) + ks * 32);
            uint32_t bf[2][4];           // pair p -> {nt(2p).b0, b1, nt(2p+1).b0, b1}
            #pragma unroll
            for (int p = 0; p < 2; p++)
                ldsm4(bf[p], oB + p * (16 * SK * 4) + ks * 32);
            #pragma unroll
            for (int mt = 0; mt < MT; mt++)
                #pragma unroll
                for (int nt = 0; nt < 4; nt++)
                    mma8(cc[mt][nt], af[mt], &bf[nt >> 1][(nt & 1) * 2]);
        }
    }

    // Epilogue
    #pragma unroll
    for (int mt = 0; mt < MT; mt++) {
        int r0 = wm * (MT * 16) + mt * 16 + gp;
        int r1 = r0 + 8;
        #pragma unroll
        for (int nt = 0; nt < 4; nt++) {
            int col = n0 + wn * 32 + nt * 8 + tg * 2;
            if (ROUTED) {
                if (m0 + r0 < ne) {
                    float* yr = Y + (size_t)stok[r0] * H_ + col;
                    atomicAdd(yr,     cc[mt][nt][0]);
                    atomicAdd(yr + 1, cc[mt][nt][1]);
                }
                if (m0 + r1 < ne) {
                    float* yr = Y + (size_t)stok[r1] * H_ + col;
                    atomicAdd(yr,     cc[mt][nt][2]);
                    atomicAdd(yr + 1, cc[mt][nt][3]);
                }
            } else {
                float2 o0 = make_float2(cc[mt][nt][0], cc[mt][nt][1]);
                float2 o1 = make_float2(cc[mt][nt][2], cc[mt][nt][3]);
                *(float2*)(Y + (size_t)(m0 + r0) * H_ + col) = o0;
                *(float2*)(Y + (size_t)(m0 + r1) * H_ + col) = o1;
            }
        }
    }
}

// ---------------------------------------------------------------------------
// Launch sequence (default stream; graph-capturable: kernel launches only)
// ---------------------------------------------------------------------------
extern "C" void kernel_launch(void* const* d_in, const int* in_sizes, int n_in,
                              void* d_out, int out_size) {
    (void)in_sizes; (void)n_in; (void)out_size;
    const float* x   = (const float*)d_in[0];
    const float* gw  = (const float*)d_in[1];
    const float* gb  = (const float*)d_in[2];
    const float* gp  = (const float*)d_in[3];
    const float* up  = (const float*)d_in[4];
    const float* dp  = (const float*)d_in[5];
    const float* sgw = (const float*)d_in[6];
    const float* suw = (const float*)d_in[7];
    const float* sdw = (const float*)d_in[8];
    float* y = (float*)d_out;

    zero_cnt_kernel<<<1, 32>>>();
    gate_kernel<<<T_, 128>>>(x, gw, gb);

    // activations
    mlp1_tc<false, IS_><<<dim3(IS_ / 64, T_ / 128),     256>>>(x, sgw, suw);
    mlp1_tc<true,  I_ ><<<dim3(I_  / 64, T_ / 128, E_), 256>>>(x, gp,  up);

    // down: shared writes Y (init), routed accumulates on top
    down_tc<false, IS_, 2><<<dim3(H_ / 128, T_ / 64),      256>>>(sdw, y);
    down_tc<true,  I_,  4><<<dim3(H_ / 128, T_ / 128, E_), 256>>>(dp,  y);
}